// round 16
// baseline (speedup 1.0000x reference)
#include <cuda_runtime.h>
#include <cuda_fp16.h>
#include <cstdint>

#define BATCH  4
#define SEQ    4096
#define HID    4096
#define OUTF   4096
#define RANK   64
#define NADAPT 8
#define KSPLIT 4

// ---------------------------------------------------------------------------
// Global scratch
// g_part: fp32 split-K partials [kp][b][s][r]
// g_bx:  fp16 [b][s][r]     g_at: fp16 [a][o][r]  (K-major, packed half2)
// ---------------------------------------------------------------------------
__device__ __align__(16) float    g_part[(size_t)KSPLIT * BATCH * SEQ * RANK];
__device__ __align__(16) uint32_t g_bx[BATCH * SEQ * RANK / 2];
__device__ __align__(16) uint32_t g_at[NADAPT * OUTF * RANK / 2];

#define SW128(b) ((b) ^ (((b) >> 3) & 0x70))

__device__ __forceinline__ uint32_t smem_u32(const void* p) {
    uint32_t a;
    asm("{ .reg .u64 t; cvta.to.shared.u64 t, %1; cvt.u32.u64 %0, t; }"
        : "=r"(a) : "l"(p));
    return a;
}

__device__ __forceinline__ void ldsm4(uint32_t r[4], uint32_t addr) {
    asm volatile("ldmatrix.sync.aligned.m8n8.x4.shared.b16 {%0,%1,%2,%3}, [%4];"
        : "=r"(r[0]), "=r"(r[1]), "=r"(r[2]), "=r"(r[3]) : "r"(addr));
}

__device__ __forceinline__ void mma16816(float c[4], const uint32_t a[4],
                                         uint32_t b0, uint32_t b1) {
    asm volatile(
        "mma.sync.aligned.m16n8k16.row.col.f32.f16.f16.f32 "
        "{%0,%1,%2,%3}, {%4,%5,%6,%7}, {%8,%9}, {%0,%1,%2,%3};"
        : "+f"(c[0]), "+f"(c[1]), "+f"(c[2]), "+f"(c[3])
        : "r"(a[0]), "r"(a[1]), "r"(a[2]), "r"(a[3]), "r"(b0), "r"(b1));
}

// pack two floats -> one f16x2 word (lo = a, hi = b)
__device__ __forceinline__ uint32_t packh2(float a, float b) {
    uint32_t r;
    asm("cvt.rn.f16x2.f32 %0, %1, %2;" : "=r"(r) : "f"(b), "f"(a));
    return r;
}

// streaming (evict-first) stores/loads for zero-reuse data
__device__ __forceinline__ void stg_cs_f2(float* p, float2 v) {
    asm volatile("st.global.cs.v2.f32 [%0], {%1, %2};"
                 :: "l"(p), "f"(v.x), "f"(v.y) : "memory");
}
__device__ __forceinline__ float4 ldg_cs_f4(const float4* p) {
    float4 v;
    asm volatile("ld.global.cs.v4.f32 {%0,%1,%2,%3}, [%4];"
                 : "=f"(v.x), "=f"(v.y), "=f"(v.z), "=f"(v.w) : "l"(p));
    return v;
}

#define CPASYNC16(sm, gp) \
    asm volatile("cp.async.cg.shared.global [%0], [%1], 16;" \
                 :: "r"(sm), "l"(gp) : "memory")
#define CPASYNC_COMMIT() asm volatile("cp.async.commit_group;" ::: "memory")
#define CPASYNC_WAIT0()  asm volatile("cp.async.wait_group 0;" ::: "memory")

// ===========================================================================
// prep_A: A[a][r][o] fp32 -> g_at [a][o][r] fp16 (K-major). grid 256.
// ===========================================================================
__global__ __launch_bounds__(256) void lora_prep_a(const float* __restrict__ A) {
    __shared__ float As[64][132];
    const int tid = threadIdx.x;
    const int a  = blockIdx.x >> 5;
    const int o0 = (blockIdx.x & 31) * 128;

    #pragma unroll
    for (int i = 0; i < 8; ++i) {
        int idx = tid + i * 256;
        int r = idx >> 5, og = idx & 31;
        *(float4*)&As[r][og * 4] =
            *(const float4*)(A + (size_t)a * RANK * OUTF + (size_t)r * OUTF + o0 + og * 4);
    }
    __syncthreads();

    const int o = tid >> 1, r0 = (tid & 1) * 32;
    __align__(16) uint32_t hb[16];
    #pragma unroll
    for (int j = 0; j < 16; ++j)
        hb[j] = packh2(As[r0 + 2 * j][o], As[r0 + 2 * j + 1][o]);

    size_t base = ((size_t)(a * OUTF + o0 + o) * RANK + r0) / 2;
    #pragma unroll
    for (int q = 0; q < 4; ++q)
        *(uint4*)(g_at + base + q * 4) = *(uint4*)(hb + q * 4);
}

// ===========================================================================
// Stage 1 (per batch-pair): partial[kp][b][s][r] += x @ B   [R14-proven body]
// grid (32, 2, 4): x=m-tile, y=batch-in-pair, z=kp. 256 thr, 48 KB, 2/SM.
// ===========================================================================
#define S1_X   0
#define S1_B   16384
#define S1_BUF 24576
#define S1_SMEM (2 * S1_BUF)
#define S1_KC   (HID / KSPLIT / 64)     // 16 chunks

__global__ __launch_bounds__(256, 2) void lora_s1(
    const float* __restrict__ x, const int* __restrict__ ids,
    const float* __restrict__ Bw, int pair)
{
    extern __shared__ __align__(128) uint8_t sm1[];
    const int tid = threadIdx.x, lane = tid & 31, wid = tid >> 5;
    const int wm = wid & 3, wn = wid >> 2;           // 4M x 2N warps
    const int b = pair * 2 + blockIdx.y;
    const int kp = blockIdx.z;
    const int a = ids[b];
    const int m0 = blockIdx.x * 128;
    const int k0 = kp * (HID / KSPLIT);

    const uint32_t smb = smem_u32(sm1);
    const int lr = lane & 15;
    const uint32_t lcol = (uint32_t)(lane >> 4) * 16;

    uint32_t aterm[2], axor[2], bterm[2], bxor[2];
    #pragma unroll
    for (int t = 0; t < 2; ++t) {
        int ar = wm * 32 + t * 16 + lr;
        aterm[t] = (uint32_t)ar * 128; axor[t] = (uint32_t)(ar & 7) << 4;
        int br = wn * 32 + t * 16 + lr;
        bterm[t] = (uint32_t)br * 128; bxor[t] = (uint32_t)(br & 7) << 4;
    }

    float acc[2][4][4];
    #pragma unroll
    for (int i = 0; i < 2; ++i)
        #pragma unroll
        for (int j = 0; j < 4; ++j)
            #pragma unroll
            for (int k = 0; k < 4; ++k) acc[i][j][k] = 0.f;

    const int xkg = tid & 15;
    const int bih = tid & 31;
    const int brg0 = tid >> 5;

    float4 xv[8], bv0[2], bv1[2];

    // ---- prefetch chunk 0 ----
    #pragma unroll
    for (int i = 0; i < 8; ++i) {
        int m = (tid + i * 256) >> 4;
        xv[i] = *(const float4*)(x + (size_t)(b * SEQ + m0 + m) * HID + k0 + xkg * 4);
    }
    #pragma unroll
    for (int i = 0; i < 2; ++i) {
        const float* p = Bw + (size_t)(k0 + 2 * bih) * (NADAPT * RANK) + a * RANK
                       + (brg0 + i * 8) * 4;
        bv0[i] = *(const float4*)p;
        bv1[i] = *(const float4*)(p + NADAPT * RANK);
    }

    // ---- convert chunk 0 into buf 0 ----
    #pragma unroll
    for (int i = 0; i < 8; ++i) {
        int m = (tid + i * 256) >> 4;
        uint32_t s0 = SW128((uint32_t)m * 128 + xkg * 8);
        *(uint2*)(sm1 + S1_X + s0) =
            make_uint2(packh2(xv[i].x, xv[i].y), packh2(xv[i].z, xv[i].w));
    }
    #pragma unroll
    for (int i = 0; i < 2; ++i) {
        const float* f0 = &bv0[i].x;
        const float* f1 = &bv1[i].x;
        #pragma unroll
        for (int j = 0; j < 4; ++j) {
            uint32_t so = SW128((uint32_t)((brg0 + i * 8) * 4 + j) * 128 + bih * 4);
            *(uint32_t*)(sm1 + S1_B + so) = packh2(f0[j], f1[j]);
        }
    }
    __syncthreads();

    for (int it = 0; it < S1_KC; ++it) {
        const uint32_t pb = (uint32_t)(it & 1) * S1_BUF;

        if (it + 1 < S1_KC) {
            int kc = k0 + (it + 1) * 64;
            #pragma unroll
            for (int i = 0; i < 8; ++i) {
                int m = (tid + i * 256) >> 4;
                xv[i] = *(const float4*)(x + (size_t)(b * SEQ + m0 + m) * HID + kc + xkg * 4);
            }
            #pragma unroll
            for (int i = 0; i < 2; ++i) {
                const float* p = Bw + (size_t)(kc + 2 * bih) * (NADAPT * RANK) + a * RANK
                               + (brg0 + i * 8) * 4;
                bv0[i] = *(const float4*)p;
                bv1[i] = *(const float4*)(p + NADAPT * RANK);
            }
        }

        #pragma unroll
        for (int ks = 0; ks < 4; ++ks) {
            uint32_t cb = lcol + (uint32_t)ks * 32;
            uint32_t a0[4], a1[4], b0[4], b1[4];
            ldsm4(a0, smb + S1_X + pb + aterm[0] + (cb ^ axor[0]));
            ldsm4(a1, smb + S1_X + pb + aterm[1] + (cb ^ axor[1]));
            ldsm4(b0, smb + S1_B + pb + bterm[0] + (cb ^ bxor[0]));
            ldsm4(b1, smb + S1_B + pb + bterm[1] + (cb ^ bxor[1]));

            mma16816(acc[0][0], a0, b0[0], b0[2]);
            mma16816(acc[0][1], a0, b0[1], b0[3]);
            mma16816(acc[0][2], a0, b1[0], b1[2]);
            mma16816(acc[0][3], a0, b1[1], b1[3]);
            mma16816(acc[1][0], a1, b0[0], b0[2]);
            mma16816(acc[1][1], a1, b0[1], b0[3]);
            mma16816(acc[1][2], a1, b1[0], b1[2]);
            mma16816(acc[1][3], a1, b1[1], b1[3]);
        }

        if (it + 1 < S1_KC) {
            const uint32_t qb = pb ^ S1_BUF;
            #pragma unroll
            for (int i = 0; i < 8; ++i) {
                int m = (tid + i * 256) >> 4;
                uint32_t s0 = SW128((uint32_t)m * 128 + xkg * 8);
                *(uint2*)(sm1 + S1_X + qb + s0) =
                    make_uint2(packh2(xv[i].x, xv[i].y), packh2(xv[i].z, xv[i].w));
            }
            #pragma unroll
            for (int i = 0; i < 2; ++i) {
                const float* f0 = &bv0[i].x;
                const float* f1 = &bv1[i].x;
                #pragma unroll
                for (int j = 0; j < 4; ++j) {
                    uint32_t so = SW128((uint32_t)((brg0 + i * 8) * 4 + j) * 128 + bih * 4);
                    *(uint32_t*)(sm1 + S1_B + qb + so) = packh2(f0[j], f1[j]);
                }
            }
        }
        __syncthreads();
    }

    float* pp = g_part + (size_t)(kp * BATCH + b) * SEQ * RANK;
    #pragma unroll
    for (int mt = 0; mt < 2; ++mt)
        #pragma unroll
        for (int nt = 0; nt < 4; ++nt)
            #pragma unroll
            for (int rh = 0; rh < 2; ++rh) {
                int s = m0 + wm * 32 + mt * 16 + rh * 8 + (lane >> 2);
                int r = wn * 32 + nt * 8 + 2 * (lane & 3);
                float2 v = { acc[mt][nt][2 * rh], acc[mt][nt][2 * rh + 1] };
                stg_cs_f2(pp + (size_t)s * RANK + r, v);
            }
}

// ===========================================================================
// bx_reduce (per batch-pair): sum 4 split-K partials -> fp16 g_bx
// grid 512 CTAs: b = pair*2 + (bx>>8), 64K float4 per batch.
// ===========================================================================
__global__ __launch_bounds__(256) void lora_bx_reduce(int pair) {
    const int b = pair * 2 + (blockIdx.x >> 8);
    const size_t SR4 = (size_t)SEQ * RANK / 4;           // 65536 float4/batch
    const size_t gid = (size_t)(blockIdx.x & 255) * 256 + threadIdx.x;
    const size_t plane = (size_t)BATCH * SR4;
    const float4* p = (const float4*)g_part + (size_t)b * SR4 + gid;
    float4 v0 = ldg_cs_f4(p);
    float4 v1 = ldg_cs_f4(p + plane);
    float4 v2 = ldg_cs_f4(p + 2 * plane);
    float4 v3 = ldg_cs_f4(p + 3 * plane);
    float4 s;
    s.x = (v0.x + v1.x) + (v2.x + v3.x);
    s.y = (v0.y + v1.y) + (v2.y + v3.y);
    s.z = (v0.z + v1.z) + (v2.z + v3.z);
    s.w = (v0.w + v1.w) + (v2.w + v3.w);
    ((uint2*)g_bx)[(size_t)b * SR4 + gid] =
        make_uint2(packh2(s.x, s.y), packh2(s.z, s.w));
}

// ===========================================================================
// Stage 2 (per batch-pair): out = Bx @ At / 64   [R12-proven body]
// grid (32, 32, 2): z=batch-in-pair. 512 thr, 32 KB, 2/SM.
// ===========================================================================
#define S2_X 0
#define S2_A 16384
#define S2_SMEM 32768

__global__ __launch_bounds__(512, 2) void lora_s2(
    const int* __restrict__ ids, float* __restrict__ out, int pair)
{
    extern __shared__ __align__(128) uint8_t sm2[];
    const int tid = threadIdx.x, lane = tid & 31, wid = tid >> 5;
    const int wm = wid & 3, wn = wid >> 2;           // 4M x 4N warps
    const int o0 = blockIdx.x * 128, m0 = blockIdx.y * 128;
    const int b = pair * 2 + blockIdx.z;
    const int a = ids[b];

    const uint32_t smb = smem_u32(sm2);

    #pragma unroll
    for (int i = 0; i < 2; ++i) {
        int idx = tid + i * 512;
        int row = idx >> 3, rg = idx & 7;
        uint32_t so = SW128((uint32_t)row * 128 + rg * 16);
        size_t bx = (size_t)(b * SEQ + m0 + row) * 8 + rg;
        size_t at = (size_t)(a * OUTF + o0 + row) * 8 + rg;
        CPASYNC16(smb + S2_X + so, (const uint4*)g_bx + bx);
        CPASYNC16(smb + S2_A + so, (const uint4*)g_at + at);
    }
    CPASYNC_COMMIT();
    CPASYNC_WAIT0();
    __syncthreads();

    const int lr = lane & 15;
    const uint32_t lcol = (uint32_t)(lane >> 4) * 16;

    uint32_t aterm[2], axor[2], bterm[2], bxor[2];
    #pragma unroll
    for (int t = 0; t < 2; ++t) {
        int ar = wm * 32 + t * 16 + lr;
        aterm[t] = (uint32_t)ar * 128; axor[t] = (uint32_t)(ar & 7) << 4;
        int br = wn * 32 + t * 16 + lr;
        bterm[t] = (uint32_t)br * 128; bxor[t] = (uint32_t)(br & 7) << 4;
    }

    float acc[2][4][4];
    #pragma unroll
    for (int i = 0; i < 2; ++i)
        #pragma unroll
        for (int j = 0; j < 4; ++j)
            #pragma unroll
            for (int k = 0; k < 4; ++k) acc[i][j][k] = 0.f;

    #pragma unroll
    for (int ks = 0; ks < 4; ++ks) {
        uint32_t cb = lcol + (uint32_t)ks * 32;
        uint32_t a0[4], a1[4], b0[4], b1[4];
        ldsm4(a0, smb + S2_X + aterm[0] + (cb ^ axor[0]));
        ldsm4(a1, smb + S2_X + aterm[1] + (cb ^ axor[1]));
        ldsm4(b0, smb + S2_A + bterm[0] + (cb ^ bxor[0]));
        ldsm4(b1, smb + S2_A + bterm[1] + (cb ^ bxor[1]));

        mma16816(acc[0][0], a0, b0[0], b0[2]);
        mma16816(acc[0][1], a0, b0[1], b0[3]);
        mma16816(acc[0][2], a0, b1[0], b1[2]);
        mma16816(acc[0][3], a0, b1[1], b1[3]);
        mma16816(acc[1][0], a1, b0[0], b0[2]);
        mma16816(acc[1][1], a1, b0[1], b0[3]);
        mma16816(acc[1][2], a1, b1[0], b1[2]);
        mma16816(acc[1][3], a1, b1[1], b1[3]);
    }

    const float sc = 1.0f / (float)RANK;
    #pragma unroll
    for (int mt = 0; mt < 2; ++mt)
        #pragma unroll
        for (int nt = 0; nt < 4; ++nt) {
            int row = m0 + wm * 32 + mt * 16 + (lane >> 2);
            int col = o0 + wn * 32 + nt * 8 + 2 * (lane & 3);
            float2 v0 = { acc[mt][nt][0] * sc, acc[mt][nt][1] * sc };
            float2 v1 = { acc[mt][nt][2] * sc, acc[mt][nt][3] * sc };
            stg_cs_f2(out + (size_t)(b * SEQ + row)     * OUTF + col, v0);
            stg_cs_f2(out + (size_t)(b * SEQ + row + 8) * OUTF + col, v1);
        }
}

// ===========================================================================
// Launch: batch-pair pipeline across two streams (fork/join via events,
// graph-capturable). Falls back to sequential if stream/event setup fails.
// ===========================================================================
extern "C" void kernel_launch(void* const* d_in, const int* in_sizes, int n_in,
                              void* d_out, int out_size)
{
    const float* x   = (const float*)d_in[0];
    const int*   ids = (const int*)  d_in[1];
    const float* A   = (const float*)d_in[2];
    const float* Bw  = (const float*)d_in[3];
    float* out = (float*)d_out;

    cudaFuncSetAttribute(lora_s1, cudaFuncAttributeMaxDynamicSharedMemorySize, S1_SMEM);
    cudaFuncSetAttribute(lora_s2, cudaFuncAttributeMaxDynamicSharedMemorySize, S2_SMEM);

    cudaStream_t S = nullptr;
    cudaEvent_t eFork = nullptr, eJoin = nullptr, e0 = nullptr, e1 = nullptr;
    bool ok = (cudaStreamCreateWithFlags(&S, cudaStreamNonBlocking) == cudaSuccess);
    if (ok) ok = (cudaEventCreateWithFlags(&eFork, cudaEventDisableTiming) == cudaSuccess);
    if (ok) ok = (cudaEventCreateWithFlags(&eJoin, cudaEventDisableTiming) == cudaSuccess);
    if (ok) ok = (cudaEventCreateWithFlags(&e0,    cudaEventDisableTiming) == cudaSuccess);
    if (ok) ok = (cudaEventCreateWithFlags(&e1,    cudaEventDisableTiming) == cudaSuccess);

    if (ok) {
        // fork side stream off the captured (default) stream
        cudaEventRecord(eFork, 0);
        cudaStreamWaitEvent(S, eFork, 0);
        lora_prep_a<<<256, 256, 0, S>>>(A);                 // overlaps s1(pair 0)

        // pair 0 on L
        lora_s1<<<dim3(SEQ / 128, 2, KSPLIT), 256, S1_SMEM, 0>>>(x, ids, Bw, 0);
        lora_bx_reduce<<<512, 256, 0, 0>>>(0);
        cudaEventRecord(e0, 0);

        // pair 1 on L (overlaps s2(pair 0) on S)
        lora_s1<<<dim3(SEQ / 128, 2, KSPLIT), 256, S1_SMEM, 0>>>(x, ids, Bw, 1);
        lora_bx_reduce<<<512, 256, 0, 0>>>(1);
        cudaEventRecord(e1, 0);

        cudaStreamWaitEvent(S, e0, 0);
        lora_s2<<<dim3(OUTF / 128, SEQ / 128, 2), 512, S2_SMEM, S>>>(ids, out, 0);
        cudaStreamWaitEvent(S, e1, 0);
        lora_s2<<<dim3(OUTF / 128, SEQ / 128, 2), 512, S2_SMEM, S>>>(ids, out, 1);

        // join back into the captured stream
        cudaEventRecord(eJoin, S);
        cudaStreamWaitEvent(0, eJoin, 0);
    } else {
        // sequential fallback (R14-equivalent schedule)
        lora_prep_a<<<256, 256>>>(A);
        lora_s1<<<dim3(SEQ / 128, 2, KSPLIT), 256, S1_SMEM>>>(x, ids, Bw, 0);
        lora_bx_reduce<<<512, 256>>>(0);
        lora_s1<<<dim3(SEQ / 128, 2, KSPLIT), 256, S1_SMEM>>>(x, ids, Bw, 1);
        lora_bx_reduce<<<512, 256>>>(1);
        lora_s2<<<dim3(OUTF / 128, SEQ / 128, 2), 512, S2_SMEM>>>(ids, out, 0);
        lora_s2<<<dim3(OUTF / 128, SEQ / 128, 2), 512, S2_SMEM>>>(ids, out, 1);
    }
}